// round 1
// baseline (speedup 1.0000x reference)
#include <cuda_runtime.h>
#include <math.h>

#define B_  4
#define T_  2048
#define D_  1024
#define NH_ 16
#define HD_ 64
#define BT_ (B_*T_)

// Scratch: [B, nh, T, hd] layouts (head-major so attention batches are contiguous)
__device__ float g_q[B_*NH_*T_*HD_];
__device__ float g_k[B_*NH_*T_*HD_];
__device__ float g_v[B_*NH_*T_*HD_];
__device__ float g_attn[B_*NH_*T_*HD_];

// ------------------------- SGEMM config -------------------------
#define BM 128
#define BN 128
#define BK 8
#define TM 8
#define TN 8

// Fused QKV projection: C = x @ W + b for W in {Wq, Wk, Wv} via blockIdx.z.
// Epilogue scatters to [B, nh, T, hd].
__global__ __launch_bounds__(256) void qkv_kernel(
    const float* __restrict__ x,
    const float* __restrict__ Wq, const float* __restrict__ bq,
    const float* __restrict__ Wk, const float* __restrict__ bk,
    const float* __restrict__ Wv, const float* __restrict__ bv)
{
    const float* W; const float* bias; float* out;
    if (blockIdx.z == 0)      { W = Wq; bias = bq; out = g_q; }
    else if (blockIdx.z == 1) { W = Wk; bias = bk; out = g_k; }
    else                      { W = Wv; bias = bv; out = g_v; }

    __shared__ float As[BK][BM];
    __shared__ float Bs[BK][BN];
    const int tid = threadIdx.x;
    const int tx = tid & 15, ty = tid >> 4;
    const int rowC = blockIdx.y * BM;
    const int colC = blockIdx.x * BN;
    const int a_row = tid >> 1, a_col = (tid & 1) * 4;
    const int b_row = tid >> 5, b_col = (tid & 31) * 4;

    float acc[TM][TN] = {};
    for (int k0 = 0; k0 < D_; k0 += BK) {
        float4 av = *reinterpret_cast<const float4*>(
            &x[(size_t)(rowC + a_row) * D_ + k0 + a_col]);
        As[a_col+0][a_row] = av.x;
        As[a_col+1][a_row] = av.y;
        As[a_col+2][a_row] = av.z;
        As[a_col+3][a_row] = av.w;
        *reinterpret_cast<float4*>(&Bs[b_row][b_col]) =
            *reinterpret_cast<const float4*>(&W[(size_t)(k0 + b_row) * D_ + colC + b_col]);
        __syncthreads();
#pragma unroll
        for (int kk = 0; kk < BK; kk++) {
            float af[TM], bf[TN];
#pragma unroll
            for (int i = 0; i < TM; i++) af[i] = As[kk][ty*TM + i];
#pragma unroll
            for (int j = 0; j < TN; j++) bf[j] = Bs[kk][tx*TN + j];
#pragma unroll
            for (int i = 0; i < TM; i++)
#pragma unroll
                for (int j = 0; j < TN; j++)
                    acc[i][j] = fmaf(af[i], bf[j], acc[i][j]);
        }
        __syncthreads();
    }
#pragma unroll
    for (int i = 0; i < TM; i++) {
        int m = rowC + ty*TM + i;
        int b = m >> 11, t = m & (T_ - 1);
#pragma unroll
        for (int j = 0; j < TN; j++) {
            int n = colC + tx*TN + j;
            int h = n >> 6, c = n & 63;
            out[(((size_t)(b*NH_ + h)) * T_ + t) * HD_ + c] = acc[i][j] + bias[n];
        }
    }
}

// Output projection: C = ctx @ Wp + bp, where ctx[m, k] is gathered from
// g_attn's [B, nh, T, hd] layout (m = b*T+t, k = h*64+c).
__global__ __launch_bounds__(256) void proj_kernel(
    const float* __restrict__ Wp, const float* __restrict__ bp,
    float* __restrict__ outC)
{
    __shared__ float As[BK][BM];
    __shared__ float Bs[BK][BN];
    const int tid = threadIdx.x;
    const int tx = tid & 15, ty = tid >> 4;
    const int rowC = blockIdx.y * BM;
    const int colC = blockIdx.x * BN;
    const int a_row = tid >> 1, a_col = (tid & 1) * 4;
    const int b_row = tid >> 5, b_col = (tid & 31) * 4;

    const int m_g = rowC + a_row;
    const int b_g = m_g >> 11, t_g = m_g & (T_ - 1);

    float acc[TM][TN] = {};
    for (int k0 = 0; k0 < D_; k0 += BK) {
        int k = k0 + a_col;
        int h = k >> 6, c = k & 63;   // float4 never crosses a 64-wide head boundary
        float4 av = *reinterpret_cast<const float4*>(
            &g_attn[(((size_t)(b_g*NH_ + h)) * T_ + t_g) * HD_ + c]);
        As[a_col+0][a_row] = av.x;
        As[a_col+1][a_row] = av.y;
        As[a_col+2][a_row] = av.z;
        As[a_col+3][a_row] = av.w;
        *reinterpret_cast<float4*>(&Bs[b_row][b_col]) =
            *reinterpret_cast<const float4*>(&Wp[(size_t)(k0 + b_row) * D_ + colC + b_col]);
        __syncthreads();
#pragma unroll
        for (int kk = 0; kk < BK; kk++) {
            float af[TM], bf[TN];
#pragma unroll
            for (int i = 0; i < TM; i++) af[i] = As[kk][ty*TM + i];
#pragma unroll
            for (int j = 0; j < TN; j++) bf[j] = Bs[kk][tx*TN + j];
#pragma unroll
            for (int i = 0; i < TM; i++)
#pragma unroll
                for (int j = 0; j < TN; j++)
                    acc[i][j] = fmaf(af[i], bf[j], acc[i][j]);
        }
        __syncthreads();
    }
#pragma unroll
    for (int i = 0; i < TM; i++) {
        int m = rowC + ty*TM + i;
#pragma unroll
        for (int j = 0; j < TN; j++) {
            int n = colC + tx*TN + j;
            outC[(size_t)m * D_ + n] = acc[i][j] + bp[n];
        }
    }
}

// ------------------------- Flash attention -------------------------
// Per block: one (b,h), 64 Q rows. Online softmax, causal tile skipping.
// Smem: QsT[64][65] (dim-major), KsT[64][65] (dim-major), Ps[64][65], Vs[64][64].
#define FPAD 65
#define SM_QST 0
#define SM_KST (64*FPAD)
#define SM_PS  (2*64*FPAD)
#define SM_VS  (3*64*FPAD)
#define FLASH_SMEM ((3*64*FPAD + 64*64) * 4)

__global__ __launch_bounds__(256) void flash_kernel()
{
    extern __shared__ float sm[];
    float* QsT = sm + SM_QST;
    float* KsT = sm + SM_KST;
    float* Ps  = sm + SM_PS;
    float* Vs  = sm + SM_VS;

    const int qt = blockIdx.x;        // Q tile (0..31)
    const int bh = blockIdx.y;        // batch*head (0..63)
    const float* Qb = g_q + (size_t)bh * T_ * HD_;
    const float* Kb = g_k + (size_t)bh * T_ * HD_;
    const float* Vb = g_v + (size_t)bh * T_ * HD_;
    float* Ob       = g_attn + (size_t)bh * T_ * HD_;

    const int tid = threadIdx.x;
    const int tx = tid & 15, ty = tid >> 4;
    const int r0 = ty * 4, c0 = tx * 4;

    // Load Q tile, transposed to dim-major (conflict-free: store stride 65)
#pragma unroll
    for (int i = 0; i < 16; i++) {
        int idx = tid + i * 256;
        int r = idx >> 6, c = idx & 63;
        QsT[c * FPAD + r] = Qb[(size_t)(qt*64 + r) * HD_ + c];
    }

    float o[4][4] = {};
    float mi[4], li[4];
#pragma unroll
    for (int i = 0; i < 4; i++) { mi[i] = -1e30f; li[i] = 0.0f; }

    for (int jt = 0; jt <= qt; jt++) {
        __syncthreads();   // previous iteration done reading Vs/Ps; Q visible on first iter
#pragma unroll
        for (int i = 0; i < 16; i++) {
            int idx = tid + i * 256;
            int s = idx >> 6, c = idx & 63;
            KsT[c * FPAD + s] = Kb[(size_t)(jt*64 + s) * HD_ + c];
            Vs[s * 64 + c]    = Vb[(size_t)(jt*64 + s) * HD_ + c];
        }
        __syncthreads();

        // S = Q @ K^T  (no 1/sqrt(d) scale in this module)
        float acc[4][4] = {};
#pragma unroll 4
        for (int k = 0; k < HD_; k++) {
            float qf[4], kf[4];
#pragma unroll
            for (int i = 0; i < 4; i++) qf[i] = QsT[k * FPAD + r0 + i];
#pragma unroll
            for (int j = 0; j < 4; j++) kf[j] = KsT[k * FPAD + c0 + j];
#pragma unroll
            for (int i = 0; i < 4; i++)
#pragma unroll
                for (int j = 0; j < 4; j++)
                    acc[i][j] = fmaf(qf[i], kf[j], acc[i][j]);
        }

        // Causal mask (only the diagonal tile needs it)
        if (jt == qt) {
#pragma unroll
            for (int i = 0; i < 4; i++)
#pragma unroll
                for (int j = 0; j < 4; j++)
                    if (c0 + j > r0 + i) acc[i][j] = -1e30f;
        }

        // Online softmax update (row reductions across the 16 tx-threads)
#pragma unroll
        for (int i = 0; i < 4; i++) {
            float v = fmaxf(fmaxf(acc[i][0], acc[i][1]), fmaxf(acc[i][2], acc[i][3]));
#pragma unroll
            for (int off = 8; off >= 1; off >>= 1)
                v = fmaxf(v, __shfl_xor_sync(0xffffffffu, v, off));
            float mnew = fmaxf(mi[i], v);
            float scale = __expf(mi[i] - mnew);
            float rs = 0.0f;
#pragma unroll
            for (int j = 0; j < 4; j++) {
                float p = __expf(acc[i][j] - mnew);
                acc[i][j] = p;
                rs += p;
            }
#pragma unroll
            for (int off = 8; off >= 1; off >>= 1)
                rs += __shfl_xor_sync(0xffffffffu, rs, off);
            li[i] = li[i] * scale + rs;
            mi[i] = mnew;
#pragma unroll
            for (int j = 0; j < 4; j++) o[i][j] *= scale;
        }

        // Stage P to shared
#pragma unroll
        for (int i = 0; i < 4; i++)
#pragma unroll
            for (int j = 0; j < 4; j++)
                Ps[(r0 + i) * FPAD + (c0 + j)] = acc[i][j];
        __syncthreads();

        // O += P @ V
#pragma unroll 4
        for (int s = 0; s < 64; s++) {
            float pf[4], vf[4];
#pragma unroll
            for (int i = 0; i < 4; i++) pf[i] = Ps[(r0 + i) * FPAD + s];
#pragma unroll
            for (int j = 0; j < 4; j++) vf[j] = Vs[s * 64 + c0 + j];
#pragma unroll
            for (int i = 0; i < 4; i++)
#pragma unroll
                for (int j = 0; j < 4; j++)
                    o[i][j] = fmaf(pf[i], vf[j], o[i][j]);
        }
    }

    // Normalize and write out
#pragma unroll
    for (int i = 0; i < 4; i++) {
        float inv = 1.0f / li[i];
#pragma unroll
        for (int j = 0; j < 4; j++)
            Ob[(size_t)(qt*64 + r0 + i) * HD_ + (c0 + j)] = o[i][j] * inv;
    }
}

// ------------------------- launch -------------------------
extern "C" void kernel_launch(void* const* d_in, const int* in_sizes, int n_in,
                              void* d_out, int out_size)
{
    // metadata order: x, Wk, bk, Wq, bq, Wv, bv, Wp, bp
    const float* x  = (const float*)d_in[0];
    const float* Wk = (const float*)d_in[1];
    const float* bk = (const float*)d_in[2];
    const float* Wq = (const float*)d_in[3];
    const float* bq = (const float*)d_in[4];
    const float* Wv = (const float*)d_in[5];
    const float* bv = (const float*)d_in[6];
    const float* Wp = (const float*)d_in[7];
    const float* bp = (const float*)d_in[8];
    float* out = (float*)d_out;

    dim3 gq(D_/BN, BT_/BM, 3);
    qkv_kernel<<<gq, 256>>>(x, Wq, bq, Wk, bk, Wv, bv);

    cudaFuncSetAttribute(flash_kernel,
                         cudaFuncAttributeMaxDynamicSharedMemorySize, FLASH_SMEM);
    dim3 gf(T_/64, B_*NH_);
    flash_kernel<<<gf, 256, FLASH_SMEM>>>();

    dim3 gp(D_/BN, BT_/BM);
    proj_kernel<<<gp, 256>>>(Wp, bp, out);
}

// round 3
// speedup vs baseline: 1.6348x; 1.6348x over previous
#include <cuda_runtime.h>
#include <cuda_bf16.h>
#include <cstdint>
#include <math.h>

#define B_  4
#define T_  2048
#define D_  1024
#define NH_ 16
#define HD_ 64
#define BT_ (B_*T_)
#define KP  3072          // packed contraction length = 3*D_

// ------------------------- scratch -------------------------
__device__ __align__(128) __nv_bfloat16 g_xp[(size_t)BT_*KP];     // x packed (A-side)
__device__ __align__(128) __nv_bfloat16 g_wp[4][(size_t)D_*KP];   // W packed transposed [n][3k] (B-side)
__device__ __align__(128) __nv_bfloat16 g_ap[(size_t)BT_*KP];     // attn out packed (A-side)
__device__ float g_q[(size_t)B_*NH_*T_*HD_];
__device__ float g_k[(size_t)B_*NH_*T_*HD_];
__device__ float g_v[(size_t)B_*NH_*T_*HD_];

// ------------------------- PTX helpers (compute_103-safe only) -------------------------
__device__ __forceinline__ uint32_t smem_u32(const void* p) {
    uint32_t a;
    asm("{ .reg .u64 t; cvta.to.shared.u64 t, %1; cvt.u32.u64 %0, t; }" : "=r"(a) : "l"(p));
    return a;
}
__device__ __forceinline__ void cp_async16(uint32_t s, const void* g) {
    asm volatile("cp.async.cg.shared.global [%0], [%1], 16;" :: "r"(s), "l"(g));
}
#define CP_COMMIT() asm volatile("cp.async.commit_group;" ::: "memory")
#define CP_WAIT2()  asm volatile("cp.async.wait_group 2;" ::: "memory")

__device__ __forceinline__ void ldsm4(uint32_t addr, uint32_t r[4]) {
    asm volatile("ldmatrix.sync.aligned.m8n8.x4.shared.b16 {%0,%1,%2,%3}, [%4];"
                 : "=r"(r[0]), "=r"(r[1]), "=r"(r[2]), "=r"(r[3]) : "r"(addr));
}
__device__ __forceinline__ void mma16816(float d[4], const uint32_t a[4], const uint32_t b[2]) {
    asm volatile("mma.sync.aligned.m16n8k16.row.col.f32.bf16.bf16.f32 "
                 "{%0,%1,%2,%3}, {%4,%5,%6,%7}, {%8,%9}, {%0,%1,%2,%3};"
                 : "+f"(d[0]), "+f"(d[1]), "+f"(d[2]), "+f"(d[3])
                 : "r"(a[0]), "r"(a[1]), "r"(a[2]), "r"(a[3]), "r"(b[0]), "r"(b[1]));
}

// ------------------------- pack kernels -------------------------
// A-side per scalar a: (a_hi, a_lo, a_hi); B-side: (b_hi, b_hi, b_lo).
__global__ __launch_bounds__(256) void pack_a_kernel(const float* __restrict__ X)
{
    int idx = blockIdx.x * 256 + threadIdx.x;
    size_t e = (size_t)idx * 4;
    float4 v = reinterpret_cast<const float4*>(X)[idx];
    int m = (int)(e >> 10), k = (int)(e & 1023);
    float vv[4] = {v.x, v.y, v.z, v.w};
    __nv_bfloat16 buf[12];
#pragma unroll
    for (int u = 0; u < 4; u++) {
        __nv_bfloat16 hi = __float2bfloat16(vv[u]);
        float lo = vv[u] - __bfloat162float(hi);
        buf[3*u] = hi; buf[3*u+1] = __float2bfloat16(lo); buf[3*u+2] = hi;
    }
    uint32_t* dst = reinterpret_cast<uint32_t*>(g_xp + (size_t)m * KP + 3*k);
    const uint32_t* src = reinterpret_cast<const uint32_t*>(buf);
#pragma unroll
    for (int t = 0; t < 6; t++) dst[t] = src[t];
}

// Transpose-pack W[k][n] -> g_wp[z][n][3k..] with (hi, hi, lo)
__global__ __launch_bounds__(256) void pack_w_kernel(
    const float* __restrict__ Wq, const float* __restrict__ Wk,
    const float* __restrict__ Wv, const float* __restrict__ Wp)
{
    const float* W = (blockIdx.z == 0) ? Wq : (blockIdx.z == 1) ? Wk :
                     (blockIdx.z == 2) ? Wv : Wp;
    __nv_bfloat16* out = g_wp[blockIdx.z];
    __shared__ float tile[32][33];
    const int tid = threadIdx.x;
    const int n0 = blockIdx.x * 32, k0 = blockIdx.y * 32;
#pragma unroll
    for (int i = 0; i < 4; i++) {
        int kk = (tid >> 5) + i * 8;
        tile[kk][tid & 31] = W[(size_t)(k0 + kk) * D_ + n0 + (tid & 31)];
    }
    __syncthreads();
#pragma unroll
    for (int i = 0; i < 4; i++) {
        int nn = (tid >> 5) + i * 8;
        int kl = tid & 31;
        float v = tile[kl][nn];
        __nv_bfloat16 hi = __float2bfloat16(v);
        float lo = v - __bfloat162float(hi);
        size_t base = (size_t)(n0 + nn) * KP + 3 * (k0 + kl);
        out[base] = hi; out[base + 1] = hi; out[base + 2] = __float2bfloat16(lo);
    }
}

// ------------------------- HMMA GEMM (128x128, BK=32, 4-stage cp.async) -------------------------
#define STAGE_BYTES 16384   // A 8KB + B 8KB
#define GSMEM (4 * STAGE_BYTES)
#define NKITER (KP / 32)    // 96

// smem tile row = 64B (32 bf16), granule swizzle: g ^= (r>>1)&3  -> conflict-free ldsm & stores
__device__ __forceinline__ uint32_t sw_off(int r, int g) {
    return (uint32_t)(r * 64 + ((g ^ ((r >> 1) & 3)) << 4));
}

__device__ __forceinline__ void load_stage(uint32_t sbuf,
                                           const __nv_bfloat16* __restrict__ A,
                                           const __nv_bfloat16* __restrict__ B,
                                           int kelem)
{
    const int tid = threadIdx.x;
#pragma unroll
    for (int i = 0; i < 4; i++) {
        int ch = tid + i * 256;                 // 0..1023
        int r = (ch & 511) >> 2;
        int g = ch & 3;
        const __nv_bfloat16* base = (ch & 512) ? B : A;
        uint32_t dst = sbuf + sw_off(r, g) + ((ch & 512) ? 8192u : 0u);
        cp_async16(dst, base + (size_t)r * KP + kelem + g * 8);
    }
}

// acc[mt][nt][4]: warp tile 32(M) x 64(N): 2 m16 x 8 n8
__device__ __forceinline__ void gemm_main(uint32_t smem,
                                          const __nv_bfloat16* __restrict__ A,
                                          const __nv_bfloat16* __restrict__ B,
                                          float acc[2][8][4])
{
    const int tid = threadIdx.x, lane = tid & 31, wid = tid >> 5;
    const int wm = (wid & 3) * 32, wn = (wid >> 2) * 64;

    for (int s = 0; s < 3; s++) { load_stage(smem + s * STAGE_BYTES, A, B, s * 32); CP_COMMIT(); }

    const int rA = wm + (lane & 15);
    const int rB = wn + (lane & 15);
    const int kgl = (lane >> 4) & 1;

    for (int ks = 0; ks < NKITER; ks++) {
        CP_WAIT2();
        __syncthreads();
        if (ks + 3 < NKITER)
            load_stage(smem + ((ks + 3) & 3) * STAGE_BYTES, A, B, (ks + 3) * 32);
        CP_COMMIT();

        uint32_t aS = smem + (ks & 3) * STAGE_BYTES;
        uint32_t bS = aS + 8192;
#pragma unroll
        for (int kh = 0; kh < 2; kh++) {
            const int kg = kh * 2 + kgl;
            uint32_t a[2][4], b[4][4];
#pragma unroll
            for (int mt = 0; mt < 2; mt++)
                ldsm4(aS + sw_off(rA + mt * 16, kg), a[mt]);
#pragma unroll
            for (int ng = 0; ng < 4; ng++)
                ldsm4(bS + sw_off(rB + ng * 16, kg), b[ng]);
#pragma unroll
            for (int mt = 0; mt < 2; mt++)
#pragma unroll
                for (int ng = 0; ng < 4; ng++) {
                    uint32_t b0[2] = {b[ng][0], b[ng][2]};
                    uint32_t b1[2] = {b[ng][1], b[ng][3]};
                    mma16816(acc[mt][ng * 2 + 0], a[mt], b0);
                    mma16816(acc[mt][ng * 2 + 1], a[mt], b1);
                }
        }
    }
}

__global__ __launch_bounds__(256, 2) void qkv_gemm(
    const float* __restrict__ bq, const float* __restrict__ bk, const float* __restrict__ bv)
{
    extern __shared__ __align__(128) char smem[];
    uint32_t sb = smem_u32(smem);
    const int z = blockIdx.z;
    const int m0 = blockIdx.y * 128, n0 = blockIdx.x * 128;

    float acc[2][8][4] = {};
    gemm_main(sb, g_xp + (size_t)m0 * KP, g_wp[z] + (size_t)n0 * KP, acc);

    const float* bias = (z == 0) ? bq : (z == 1) ? bk : bv;
    float* out = (z == 0) ? g_q : (z == 1) ? g_k : g_v;

    const int lane = threadIdx.x & 31, wid = threadIdx.x >> 5;
    const int wm = (wid & 3) * 32, wn = (wid >> 2) * 64;
    const int row_l = lane >> 2, col_l = (lane & 3) * 2;
    const int h = (n0 + wn) >> 6;     // whole warp maps into one head (wn multiple of 64)
#pragma unroll
    for (int mt = 0; mt < 2; mt++) {
        int m = m0 + wm + mt * 16 + row_l;
        int bb = m >> 11, t = m & (T_ - 1);
        float* r0p = out + ((size_t)(bb * NH_ + h) * T_ + t) * HD_;
        float* r8p = r0p + 8 * HD_;
#pragma unroll
        for (int nt = 0; nt < 8; nt++) {
            int c = nt * 8 + col_l;
            float2 bi = *reinterpret_cast<const float2*>(&bias[n0 + wn + c]);
            float2 v0 = {acc[mt][nt][0] + bi.x, acc[mt][nt][1] + bi.y};
            float2 v1 = {acc[mt][nt][2] + bi.x, acc[mt][nt][3] + bi.y};
            *reinterpret_cast<float2*>(r0p + c) = v0;
            *reinterpret_cast<float2*>(r8p + c) = v1;
        }
    }
}

__global__ __launch_bounds__(256, 2) void proj_gemm(
    const float* __restrict__ bp, float* __restrict__ outC)
{
    extern __shared__ __align__(128) char smem[];
    uint32_t sb = smem_u32(smem);
    const int m0 = blockIdx.y * 128, n0 = blockIdx.x * 128;

    float acc[2][8][4] = {};
    gemm_main(sb, g_ap + (size_t)m0 * KP, g_wp[3] + (size_t)n0 * KP, acc);

    const int lane = threadIdx.x & 31, wid = threadIdx.x >> 5;
    const int wm = (wid & 3) * 32, wn = (wid >> 2) * 64;
    const int row_l = lane >> 2, col_l = (lane & 3) * 2;
#pragma unroll
    for (int mt = 0; mt < 2; mt++) {
        int m = m0 + wm + mt * 16 + row_l;
        float* r0p = outC + (size_t)m * D_;
        float* r8p = r0p + 8 * D_;
#pragma unroll
        for (int nt = 0; nt < 8; nt++) {
            int n = n0 + wn + nt * 8 + col_l;
            float2 bi = *reinterpret_cast<const float2*>(&bp[n]);
            float2 v0 = {acc[mt][nt][0] + bi.x, acc[mt][nt][1] + bi.y};
            float2 v1 = {acc[mt][nt][2] + bi.x, acc[mt][nt][3] + bi.y};
            *reinterpret_cast<float2*>(r0p + n) = v0;
            *reinterpret_cast<float2*>(r8p + n) = v1;
        }
    }
}

// ------------------------- Flash attention (fp32) -------------------------
#define FPAD 65
#define SM_QST 0
#define SM_KST (64*FPAD)
#define SM_PS  (2*64*FPAD)
#define SM_VS  (3*64*FPAD)
#define FLASH_SMEM ((3*64*FPAD + 64*64) * 4)

__global__ __launch_bounds__(256) void flash_kernel()
{
    extern __shared__ float sm[];
    float* QsT = sm + SM_QST;
    float* KsT = sm + SM_KST;
    float* Ps  = sm + SM_PS;
    float* Vs  = sm + SM_VS;

    const int qt = blockIdx.x;
    const int bh = blockIdx.y;
    const float* Qb = g_q + (size_t)bh * T_ * HD_;
    const float* Kb = g_k + (size_t)bh * T_ * HD_;
    const float* Vb = g_v + (size_t)bh * T_ * HD_;

    const int tid = threadIdx.x;
    const int tx = tid & 15, ty = tid >> 4;
    const int r0 = ty * 4, c0 = tx * 4;

#pragma unroll
    for (int i = 0; i < 16; i++) {
        int idx = tid + i * 256;
        int r = idx >> 6, c = idx & 63;
        QsT[c * FPAD + r] = Qb[(size_t)(qt*64 + r) * HD_ + c];
    }

    float o[4][4] = {};
    float mi[4], li[4];
#pragma unroll
    for (int i = 0; i < 4; i++) { mi[i] = -1e30f; li[i] = 0.0f; }

    for (int jt = 0; jt <= qt; jt++) {
        __syncthreads();
#pragma unroll
        for (int i = 0; i < 16; i++) {
            int idx = tid + i * 256;
            int s = idx >> 6, c = idx & 63;
            KsT[c * FPAD + s] = Kb[(size_t)(jt*64 + s) * HD_ + c];
            Vs[s * 64 + c]    = Vb[(size_t)(jt*64 + s) * HD_ + c];
        }
        __syncthreads();

        float acc[4][4] = {};
#pragma unroll 4
        for (int k = 0; k < HD_; k++) {
            float qf[4], kf[4];
#pragma unroll
            for (int i = 0; i < 4; i++) qf[i] = QsT[k * FPAD + r0 + i];
#pragma unroll
            for (int j = 0; j < 4; j++) kf[j] = KsT[k * FPAD + c0 + j];
#pragma unroll
            for (int i = 0; i < 4; i++)
#pragma unroll
                for (int j = 0; j < 4; j++)
                    acc[i][j] = fmaf(qf[i], kf[j], acc[i][j]);
        }

        if (jt == qt) {
#pragma unroll
            for (int i = 0; i < 4; i++)
#pragma unroll
                for (int j = 0; j < 4; j++)
                    if (c0 + j > r0 + i) acc[i][j] = -1e30f;
        }

#pragma unroll
        for (int i = 0; i < 4; i++) {
            float v = fmaxf(fmaxf(acc[i][0], acc[i][1]), fmaxf(acc[i][2], acc[i][3]));
#pragma unroll
            for (int off = 8; off >= 1; off >>= 1)
                v = fmaxf(v, __shfl_xor_sync(0xffffffffu, v, off));
            float mnew = fmaxf(mi[i], v);
            float scale = __expf(mi[i] - mnew);
            float rs = 0.0f;
#pragma unroll
            for (int j = 0; j < 4; j++) {
                float p = __expf(acc[i][j] - mnew);
                acc[i][j] = p;
                rs += p;
            }
#pragma unroll
            for (int off = 8; off >= 1; off >>= 1)
                rs += __shfl_xor_sync(0xffffffffu, rs, off);
            li[i] = li[i] * scale + rs;
            mi[i] = mnew;
#pragma unroll
            for (int j = 0; j < 4; j++) o[i][j] *= scale;
        }

#pragma unroll
        for (int i = 0; i < 4; i++)
#pragma unroll
            for (int j = 0; j < 4; j++)
                Ps[(r0 + i) * FPAD + (c0 + j)] = acc[i][j];
        __syncthreads();

#pragma unroll 4
        for (int s = 0; s < 64; s++) {
            float pf[4], vf[4];
#pragma unroll
            for (int i = 0; i < 4; i++) pf[i] = Ps[(r0 + i) * FPAD + s];
#pragma unroll
            for (int j = 0; j < 4; j++) vf[j] = Vs[s * 64 + c0 + j];
#pragma unroll
            for (int i = 0; i < 4; i++)
#pragma unroll
                for (int j = 0; j < 4; j++)
                    o[i][j] = fmaf(pf[i], vf[j], o[i][j]);
        }
    }

    // Epilogue: write attention output in packed-triple (A-side) form for proj GEMM
    const int bb = bh >> 4, h = bh & 15;
#pragma unroll
    for (int i = 0; i < 4; i++) {
        float inv = 1.0f / li[i];
        int t = qt * 64 + r0 + i;
        size_t m = (size_t)bb * T_ + t;
        __nv_bfloat16 pb[12];
#pragma unroll
        for (int j = 0; j < 4; j++) {
            float v = o[i][j] * inv;
            __nv_bfloat16 hi = __float2bfloat16(v);
            float lo = v - __bfloat162float(hi);
            pb[3*j] = hi; pb[3*j+1] = __float2bfloat16(lo); pb[3*j+2] = hi;
        }
        uint32_t* dst = reinterpret_cast<uint32_t*>(g_ap + m * KP + 3 * (h * 64 + c0));
        const uint32_t* src = reinterpret_cast<const uint32_t*>(pb);
#pragma unroll
        for (int tt = 0; tt < 6; tt++) dst[tt] = src[tt];
    }
}

// ------------------------- launch -------------------------
extern "C" void kernel_launch(void* const* d_in, const int* in_sizes, int n_in,
                              void* d_out, int out_size)
{
    const float* x  = (const float*)d_in[0];
    const float* Wk = (const float*)d_in[1];
    const float* bk = (const float*)d_in[2];
    const float* Wq = (const float*)d_in[3];
    const float* bq = (const float*)d_in[4];
    const float* Wv = (const float*)d_in[5];
    const float* bv = (const float*)d_in[6];
    const float* Wp = (const float*)d_in[7];
    const float* bp = (const float*)d_in[8];
    float* out = (float*)d_out;

    pack_a_kernel<<<(BT_ * D_) / (4 * 256), 256>>>(x);
    pack_w_kernel<<<dim3(32, 32, 4), 256>>>(Wq, Wk, Wv, Wp);

    cudaFuncSetAttribute(qkv_gemm, cudaFuncAttributeMaxDynamicSharedMemorySize, GSMEM);
    cudaFuncSetAttribute(proj_gemm, cudaFuncAttributeMaxDynamicSharedMemorySize, GSMEM);
    cudaFuncSetAttribute(flash_kernel, cudaFuncAttributeMaxDynamicSharedMemorySize, FLASH_SMEM);

    qkv_gemm<<<dim3(8, 64, 3), 256, GSMEM>>>(bq, bk, bv);
    flash_kernel<<<dim3(T_ / 64, B_ * NH_), 256, FLASH_SMEM>>>();
    proj_gemm<<<dim3(8, 64), 256, GSMEM>>>(bp, out);
}